// round 16
// baseline (speedup 1.0000x reference)
#include <cuda_runtime.h>
#include <cuda_fp16.h>
#include <cstdint>

#define N_LINES   8192
#define D_MODEL   768
#define HD        96
#define OVERLAP   32
#define GAP       4
#define W_KEYS    16
#define M_COMB    (N_LINES + 2*OVERLAP)   // 8256
#define M_PAD     8320                    // 65*128
#define QKV_N     (3*D_MODEL)             // 2304
#define KDIM      768
#define BK        64
#define CHUNKS    (KDIM / BK)             // 12

// work queue layout
#define N_COMB    65
#define N_W1      18
#define N_W2      6
#define G1_M      65
#define G1_N      18
#define N_G1      (G1_M * G1_N)           // 1170
#define N_ATTN    64                      // 128 lines each
#define G2_M      64
#define G2_N      6
#define N_G2      (G2_M * G2_N)           // 384
#define I_COMB    0
#define I_W1      (I_COMB + N_COMB)       // 65
#define I_W2      (I_W1 + N_W1)           // 83
#define I_G1      (I_W2 + N_W2)           // 89
#define I_ATTN    (I_G1 + N_G1)           // 1259
#define I_G2      (I_ATTN + N_ATTN)       // 1323
#define NITEMS    (I_G2 + N_G2)           // 1707

// ---- scratch (device globals; zero-init covers pad rows of comb) ----
__device__ __half g_comb[(size_t)M_PAD * KDIM];
__device__ __half g_P[(size_t)M_PAD * QKV_N];
__device__ __half g_w1[(size_t)QKV_N * KDIM];
__device__ __half g_w2[(size_t)D_MODEL * KDIM];
__device__ __half g_ctx[(size_t)N_LINES * KDIM];

struct SyncBlk {
    unsigned ctr;
    unsigned combflag[N_COMB];
    unsigned w1flag[N_W1];
    unsigned w2flag[N_W2];
    unsigned g1done[G1_M];
    unsigned Pflag[G1_M];
    unsigned ctxflag[N_ATTN];
};
__device__ SyncBlk g_sync;

// ---------------- PTX helpers ----------------
__device__ __forceinline__ uint32_t smem_u32(const void* p) {
    uint32_t a;
    asm("{ .reg .u64 t; cvta.to.shared.u64 t, %1; cvt.u32.u64 %0, t; }" : "=r"(a) : "l"(p));
    return a;
}
__device__ __forceinline__ unsigned ld_acq(const unsigned* p) {
    unsigned v;
    asm volatile("ld.acquire.gpu.u32 %0, [%1];" : "=r"(v) : "l"(p) : "memory");
    return v;
}
__device__ __forceinline__ void st_rel(unsigned* p, unsigned v) {
    asm volatile("st.release.gpu.u32 [%0], %1;" :: "l"(p), "r"(v) : "memory");
}

#define CP_ASYNC16(s, g) \
    asm volatile("cp.async.cg.shared.global [%0], [%1], 16;" :: "r"(s), "l"(g))
#define CP_COMMIT()  asm volatile("cp.async.commit_group;")
#define CP_WAIT0()   asm volatile("cp.async.wait_group 0;")
#define CP_WAIT1()   asm volatile("cp.async.wait_group 1;")

#define LDSM4(r, addr) \
    asm volatile("ldmatrix.sync.aligned.m8n8.x4.shared.b16 {%0,%1,%2,%3}, [%4];" \
        : "=r"((r)[0]), "=r"((r)[1]), "=r"((r)[2]), "=r"((r)[3]) : "r"(addr))

#define MMA16816(d, a, b0, b1) \
    asm volatile("mma.sync.aligned.m16n8k16.row.col.f32.f16.f16.f32 " \
        "{%0,%1,%2,%3}, {%4,%5,%6,%7}, {%8,%9}, {%0,%1,%2,%3};" \
        : "+f"((d)[0]), "+f"((d)[1]), "+f"((d)[2]), "+f"((d)[3]) \
        : "r"((a)[0]), "r"((a)[1]), "r"((a)[2]), "r"((a)[3]), "r"(b0), "r"(b1))

__device__ __forceinline__ uint32_t swz64(int row, int chunk) {
    return (uint32_t)(row * 128 + ((chunk ^ (row & 7)) << 4));
}

// ---------------------------------------------------------------------------
// conversion helpers (128 rows x 768 cols fp32 -> fp16), 256 threads
// ---------------------------------------------------------------------------
__device__ void conv_rows(const float* __restrict__ src, __half* __restrict__ dst,
                          int nrows, int tid)
{
    int n4 = nrows * (KDIM / 4);
    for (int i = tid; i < n4; i += 256) {
        float4 v = ((const float4*)src)[i];
        __half2* d2 = (__half2*)(dst + (size_t)i * 4);
        d2[0] = __floats2half2_rn(v.x, v.y);
        d2[1] = __floats2half2_rn(v.z, v.w);
    }
}

// comb block b: rows [b*128, ...) from begin/main/end
__device__ void comb_block(const float* mn, const float* bg, const float* ed,
                           int b, int tid)
{
    int r0 = b * 128;
    int nrows = (b == 64) ? (M_COMB - r0) : 128;   // block 64: 64 real rows
    int n4 = nrows * (KDIM / 4);
    for (int i = tid; i < n4; i += 256) {
        int row = r0 + i / (KDIM/4);
        int c4  = i % (KDIM/4);
        const float4* src;
        if (row < OVERLAP)                src = (const float4*)(bg + (size_t)row * KDIM) + c4;
        else if (row < OVERLAP + N_LINES) src = (const float4*)(mn + (size_t)(row - OVERLAP) * KDIM) + c4;
        else                              src = (const float4*)(ed + (size_t)(row - OVERLAP - N_LINES) * KDIM) + c4;
        float4 v = *src;
        __half2* d2 = (__half2*)(g_comb + (size_t)row * KDIM + c4 * 4);
        d2[0] = __floats2half2_rn(v.x, v.y);
        d2[1] = __floats2half2_rn(v.z, v.w);
    }
}

// ---------------------------------------------------------------------------
// shared GEMM tile: BM=128, BN=128, BK=64, 8 warps (2x4), warp tile 64x32,
// 3-stage cp.async. HALF_OUT: fp16 C (ldc=QKV_N, coff=0) else fp32 C.
// ---------------------------------------------------------------------------
#define STAGE_BYTES 32768
#define NSTAGE      3
#define MEGA_SMEM   (NSTAGE * STAGE_BYTES)

__device__ __forceinline__ void load_stage(uint32_t smb, int stage,
                                           const __half* A, const __half* B,
                                           int bm, int bn, int k0, int tid)
{
    const uint32_t base = smb + stage * STAGE_BYTES;
    #pragma unroll
    for (int i = 0; i < 4; i++) {
        int idx = tid + i * 256;
        int row = idx >> 3, c = idx & 7;
        const char* ga = (const char*)(A + (size_t)(bm + row) * KDIM + k0 + c * 8);
        CP_ASYNC16(base + swz64(row, c), ga);
        const char* gb = (const char*)(B + (size_t)(bn + row) * KDIM + k0 + c * 8);
        CP_ASYNC16(base + 16384 + swz64(row, c), gb);
    }
}

template <bool HALF_OUT>
__device__ void gemm_tile(char* sm, const __half* __restrict__ A,
                          const __half* __restrict__ B,
                          const float* __restrict__ bias,
                          void* __restrict__ Cv, int ldc, int coff,
                          int bm, int bn, int tid)
{
    const uint32_t smb = smem_u32(sm);
    const int lane = tid & 31;
    const int wid  = tid >> 5;
    const int wm   = wid & 1;
    const int wn   = wid >> 1;

    float acc[4][4][4];
    #pragma unroll
    for (int i = 0; i < 4; i++)
        #pragma unroll
        for (int j = 0; j < 4; j++)
            #pragma unroll
            for (int r = 0; r < 4; r++) acc[i][j][r] = 0.f;

    load_stage(smb, 0, A, B, bm, bn, 0, tid);
    CP_COMMIT();
    load_stage(smb, 1, A, B, bm, bn, BK, tid);
    CP_COMMIT();

    const int lane15 = lane & 15;
    const int aChunkSel = lane >> 4;
    const int bRow = ((lane & 16) >> 1) + (lane & 7);
    const int bChunkSel = (lane >> 3) & 1;

    int stage = 0;
    for (int c = 0; c < CHUNKS; c++) {
        if (c == CHUNKS - 1) { CP_WAIT0(); } else { CP_WAIT1(); }
        __syncthreads();
        if (c + 2 < CHUNKS) {
            int ns = stage + 2; if (ns >= NSTAGE) ns -= NSTAGE;
            load_stage(smb, ns, A, B, bm, bn, (c + 2) * BK, tid);
            CP_COMMIT();
        }
        const uint32_t base = smb + stage * STAGE_BYTES;

        #pragma unroll
        for (int ks = 0; ks < 4; ks++) {
            const int c0 = ks * 2;
            uint32_t af[4][4], bf[2][4];
            #pragma unroll
            for (int mt = 0; mt < 4; mt++) {
                int row = wm * 64 + mt * 16 + lane15;
                LDSM4(af[mt], base + swz64(row, c0 + aChunkSel));
            }
            #pragma unroll
            for (int bt = 0; bt < 2; bt++) {
                int row = wn * 32 + bt * 16 + bRow;
                LDSM4(bf[bt], base + 16384 + swz64(row, c0 + bChunkSel));
            }
            #pragma unroll
            for (int mt = 0; mt < 4; mt++)
                #pragma unroll
                for (int nt = 0; nt < 4; nt++) {
                    const uint32_t* bp = bf[nt >> 1] + ((nt & 1) << 1);
                    MMA16816(acc[mt][nt], af[mt], bp[0], bp[1]);
                }
        }
        stage++; if (stage >= NSTAGE) stage = 0;
    }
    __syncthreads();   // smem reuse safety for next item

    #pragma unroll
    for (int mt = 0; mt < 4; mt++) {
        int m0 = bm + wm * 64 + mt * 16 + (lane >> 2);
        #pragma unroll
        for (int nt = 0; nt < 4; nt++) {
            int n = bn + wn * 32 + nt * 8 + (lane & 3) * 2;
            float bx = bias[n], by = bias[n + 1];
            if (HALF_OUT) {
                __half* C = (__half*)Cv;
                *(__half2*)(C + (size_t)m0 * ldc + coff + n) =
                    __floats2half2_rn(acc[mt][nt][0] + bx, acc[mt][nt][1] + by);
                *(__half2*)(C + (size_t)(m0 + 8) * ldc + coff + n) =
                    __floats2half2_rn(acc[mt][nt][2] + bx, acc[mt][nt][3] + by);
            } else {
                float* C = (float*)Cv;
                *(float2*)(C + (size_t)m0 * ldc + coff + n) =
                    make_float2(acc[mt][nt][0] + bx, acc[mt][nt][1] + by);
                *(float2*)(C + (size_t)(m0 + 8) * ldc + coff + n) =
                    make_float2(acc[mt][nt][2] + bx, acc[mt][nt][3] + by);
            }
        }
    }
}

// ---------------------------------------------------------------------------
// attention group: 4 lines, 8 warps (2 per line), 8 lanes/head, 12 dims/lane
// ---------------------------------------------------------------------------
__device__ void attn_group(const __half* __restrict__ P, __half* __restrict__ ctx,
                           const float* __restrict__ mn, float* __restrict__ out,
                           int lbase, int tid)
{
    const int warp = tid >> 5;
    const int lane = tid & 31;
    const int n    = lbase + (warp >> 1);
    const int half = warp & 1;
    const int dimoff = half * 384 + (lane >> 3) * HD + (lane & 7) * 12;

    const float scale = rsqrtf((float)HD);

    float qf[12];
    {
        const uint2* qp = (const uint2*)(P + (size_t)(n + OVERLAP) * QKV_N + dimoff);
        #pragma unroll
        for (int t = 0; t < 3; t++) {
            uint2 u = qp[t];
            const __half2* h2 = (const __half2*)&u;
            #pragma unroll
            for (int j = 0; j < 2; j++) {
                float2 f = __half22float2(h2[j]);
                qf[t*4 + 2*j]     = f.x * scale;
                qf[t*4 + 2*j + 1] = f.y * scale;
            }
        }
    }

    float s[W_KEYS];
    #pragma unroll
    for (int w = 0; w < W_KEYS; w++) {
        int off = (w < 8) ? (-OVERLAP + GAP * w) : (GAP * (w - 7));
        const uint2* kp = (const uint2*)(P + (size_t)(n + OVERLAP + off) * QKV_N + D_MODEL + dimoff);
        float p = 0.f;
        #pragma unroll
        for (int t = 0; t < 3; t++) {
            uint2 u = kp[t];
            const __half2* h2 = (const __half2*)&u;
            #pragma unroll
            for (int j = 0; j < 2; j++) {
                float2 f = __half22float2(h2[j]);
                p = fmaf(qf[t*4 + 2*j],     f.x, p);
                p = fmaf(qf[t*4 + 2*j + 1], f.y, p);
            }
        }
        p += __shfl_xor_sync(0xffffffffu, p, 1);
        p += __shfl_xor_sync(0xffffffffu, p, 2);
        p += __shfl_xor_sync(0xffffffffu, p, 4);
        s[w] = p;
    }

    float m = s[0];
    #pragma unroll
    for (int w = 1; w < W_KEYS; w++) m = fmaxf(m, s[w]);
    float sum = 0.f;
    #pragma unroll
    for (int w = 0; w < W_KEYS; w++) { s[w] = __expf(s[w] - m); sum += s[w]; }
    float inv = 1.f / sum;

    float c[12];
    #pragma unroll
    for (int j = 0; j < 12; j++) c[j] = 0.f;
    #pragma unroll
    for (int w = 0; w < W_KEYS; w++) {
        int off = (w < 8) ? (-OVERLAP + GAP * w) : (GAP * (w - 7));
        const uint2* vp = (const uint2*)(P + (size_t)(n + OVERLAP + off) * QKV_N + 2*D_MODEL + dimoff);
        float p = s[w] * inv;
        #pragma unroll
        for (int t = 0; t < 3; t++) {
            uint2 u = vp[t];
            const __half2* h2 = (const __half2*)&u;
            #pragma unroll
            for (int j = 0; j < 2; j++) {
                float2 f = __half22float2(h2[j]);
                c[t*4 + 2*j]     = fmaf(p, f.x, c[t*4 + 2*j]);
                c[t*4 + 2*j + 1] = fmaf(p, f.y, c[t*4 + 2*j + 1]);
            }
        }
    }

    uint2* cp = (uint2*)(ctx + (size_t)n * D_MODEL + dimoff);
    #pragma unroll
    for (int t = 0; t < 3; t++) {
        uint2 u;
        __half2* h2 = (__half2*)&u;
        h2[0] = __floats2half2_rn(c[t*4 + 0], c[t*4 + 1]);
        h2[1] = __floats2half2_rn(c[t*4 + 2], c[t*4 + 3]);
        cp[t] = u;
    }

    // fused copy: 4 lines of main -> out[:, :768]
    {
        int b0 = (lbase >> 2) * 768 + tid;
        #pragma unroll
        for (int i = 0; i < 3; i++) {
            int idx = b0 + i * 256;
            int row = idx / 192, c4 = idx % 192;
            ((float4*)(out + (size_t)row * 2 * D_MODEL))[c4] =
                ((const float4*)(mn + (size_t)row * D_MODEL))[c4];
        }
    }
}

// ---------------------------------------------------------------------------
// persistent megakernel
// ---------------------------------------------------------------------------
__global__ __launch_bounds__(256, 2)
void mega_kernel(const float* __restrict__ mn,  const float* __restrict__ bg,
                 const float* __restrict__ ed,  const float* __restrict__ wqkv,
                 const float* __restrict__ bqkv,const float* __restrict__ wo,
                 const float* __restrict__ bo,  float* __restrict__ out)
{
    extern __shared__ char sm[];
    __shared__ unsigned s_item;
    const int tid = threadIdx.x;

    const __half* P  = (const __half*)g_P;
    __half* CX = g_ctx;

    for (;;) {
        __syncthreads();
        if (tid == 0) s_item = atomicAdd(&g_sync.ctr, 1u);
        __syncthreads();
        unsigned it = s_item;
        if (it >= NITEMS) return;

        if (it < I_W1) {                         // comb block
            int b = it;
            comb_block(mn, bg, ed, b, tid);
            __threadfence();
            __syncthreads();
            if (tid == 0) st_rel(&g_sync.combflag[b], 1u);
        } else if (it < I_W2) {                  // w1 block
            int b = it - I_W1;
            conv_rows(wqkv + (size_t)b * 128 * KDIM, g_w1 + (size_t)b * 128 * KDIM, 128, tid);
            __threadfence();
            __syncthreads();
            if (tid == 0) st_rel(&g_sync.w1flag[b], 1u);
        } else if (it < I_G1) {                  // w2 block
            int b = it - I_W2;
            conv_rows(wo + (size_t)b * 128 * KDIM, g_w2 + (size_t)b * 128 * KDIM, 128, tid);
            __threadfence();
            __syncthreads();
            if (tid == 0) st_rel(&g_sync.w2flag[b], 1u);
        } else if (it < I_ATTN) {                // GEMM1 tile
            int t = it - I_G1;
            int m = t / G1_N, n = t % G1_N;
            if (tid == 0) {
                while (!ld_acq(&g_sync.combflag[m])) ;
                while (!ld_acq(&g_sync.w1flag[n])) ;
            }
            __syncthreads();
            gemm_tile<true>(sm, g_comb, g_w1, bqkv, g_P, QKV_N, 0,
                            m * 128, n * 128, tid);
            __threadfence();
            __syncthreads();
            if (tid == 0) {
                unsigned old = atomicAdd(&g_sync.g1done[m], 1u);
                if (old == G1_N - 1) st_rel(&g_sync.Pflag[m], 1u);
            }
        } else if (it < I_G2) {                  // attention chunk (128 lines)
            int c = it - I_ATTN;
            if (tid == 0) {
                while (!ld_acq(&g_sync.Pflag[c])) ;
                while (!ld_acq(&g_sync.Pflag[c + 1])) ;
            }
            __syncthreads();
            for (int g = 0; g < 32; g++)
                attn_group(P, CX, mn, out, c * 128 + g * 4, tid);
            __threadfence();
            __syncthreads();
            if (tid == 0) st_rel(&g_sync.ctxflag[c], 1u);
        } else {                                 // GEMM2 tile
            int t = it - I_G2;
            int m = t / G2_N, n = t % G2_N;
            if (tid == 0) {
                while (!ld_acq(&g_sync.ctxflag[m])) ;
                while (!ld_acq(&g_sync.w2flag[n])) ;
            }
            __syncthreads();
            gemm_tile<false>(sm, g_ctx, g_w2, bo, out, 2 * D_MODEL, D_MODEL,
                             m * 128, n * 128, tid);
        }
    }
}

// ---------------------------------------------------------------------------
extern "C" void kernel_launch(void* const* d_in, const int* in_sizes, int n_in,
                              void* d_out, int out_size)
{
    const float* mn   = (const float*)d_in[0];
    const float* bg   = (const float*)d_in[1];
    const float* ed   = (const float*)d_in[2];
    const float* wqkv = (const float*)d_in[3];
    const float* bqkv = (const float*)d_in[4];
    const float* wo   = (const float*)d_in[5];
    const float* bo   = (const float*)d_in[6];
    float* out = (float*)d_out;

    static int grid = 0;
    if (!grid) {
        cudaFuncSetAttribute(mega_kernel,
                             cudaFuncAttributeMaxDynamicSharedMemorySize, MEGA_SMEM);
        int dev = 0, sms = 0, occ = 0;
        cudaGetDevice(&dev);
        cudaDeviceGetAttribute(&sms, cudaDevAttrMultiProcessorCount, dev);
        cudaOccupancyMaxActiveBlocksPerMultiprocessor(&occ, mega_kernel, 256, MEGA_SMEM);
        if (occ > 2) occ = 2;
        if (occ < 1) occ = 1;
        grid = sms * occ;
    }

    void* pSync;
    cudaGetSymbolAddress(&pSync, g_sync);
    cudaMemsetAsync(pSync, 0, sizeof(SyncBlk), 0);

    mega_kernel<<<grid, 256, MEGA_SMEM>>>(mn, bg, ed, wqkv, bqkv, wo, bo, out);
}

// round 17
// speedup vs baseline: 2.1950x; 2.1950x over previous
#include <cuda_runtime.h>
#include <cuda_fp16.h>
#include <cstdint>

#define N_LINES   8192
#define D_MODEL   768
#define HD        96
#define OVERLAP   32
#define GAP       4
#define W_KEYS    16
#define M_COMB    (N_LINES + 2*OVERLAP)   // 8256
#define M_PAD     8320                    // 65*128
#define QKV_N     (3*D_MODEL)             // 2304
#define KDIM      768
#define BK        64
#define CHUNKS    (KDIM / BK)             // 12
#define NLANES    4

// ---- scratch (device globals, padded M; zero-init covers pad rows) ----
__device__ __half g_comb[(size_t)M_PAD * KDIM];
__device__ __half g_P[(size_t)M_PAD * QKV_N];
__device__ __half g_w1[(size_t)QKV_N * KDIM];
__device__ __half g_w2[(size_t)D_MODEL * KDIM];
__device__ __half g_ctx[(size_t)N_LINES * KDIM];

// ---------------- PTX helpers ----------------
__device__ __forceinline__ uint32_t smem_u32(const void* p) {
    uint32_t a;
    asm("{ .reg .u64 t; cvta.to.shared.u64 t, %1; cvt.u32.u64 %0, t; }" : "=r"(a) : "l"(p));
    return a;
}

#define CP_ASYNC16(s, g) \
    asm volatile("cp.async.cg.shared.global [%0], [%1], 16;" :: "r"(s), "l"(g))
#define CP_COMMIT()  asm volatile("cp.async.commit_group;")
#define CP_WAIT0()   asm volatile("cp.async.wait_group 0;")
#define CP_WAIT1()   asm volatile("cp.async.wait_group 1;")

#define LDSM4(r, addr) \
    asm volatile("ldmatrix.sync.aligned.m8n8.x4.shared.b16 {%0,%1,%2,%3}, [%4];" \
        : "=r"((r)[0]), "=r"((r)[1]), "=r"((r)[2]), "=r"((r)[3]) : "r"(addr))

#define MMA16816(d, a, b0, b1) \
    asm volatile("mma.sync.aligned.m16n8k16.row.col.f32.f16.f16.f32 " \
        "{%0,%1,%2,%3}, {%4,%5,%6,%7}, {%8,%9}, {%0,%1,%2,%3};" \
        : "+f"((d)[0]), "+f"((d)[1]), "+f"((d)[2]), "+f"((d)[3]) \
        : "r"((a)[0]), "r"((a)[1]), "r"((a)[2]), "r"((a)[3]), "r"(b0), "r"(b1))

__device__ __forceinline__ uint32_t swz64(int row, int chunk) {
    return (uint32_t)(row * 128 + ((chunk ^ (row & 7)) << 4));
}

// ---------------------------------------------------------------------------
// fused prep: comb build + w1 + w2 fp32->fp16, 4 float4 per thread (MLP=4)
// ---------------------------------------------------------------------------
#define COMB4 (M_COMB * KDIM / 4)
#define W14   (QKV_N * KDIM / 4)
#define W24   (D_MODEL * KDIM / 4)
#define PREP_TOTAL (COMB4 + W14 + W24)

__global__ void prep_kernel(const float* __restrict__ mn,
                            const float* __restrict__ bg,
                            const float* __restrict__ ed,
                            const float* __restrict__ w1,
                            const float* __restrict__ w2)
{
    int base = blockIdx.x * 1024 + threadIdx.x;
    float4 v[4];
    __half* dsts[4];
    #pragma unroll
    for (int t = 0; t < 4; t++) {
        int i = base + t * 256;
        const float4* src = nullptr;
        __half* dst = nullptr;
        if (i < COMB4) {
            int row = i / (KDIM/4), c4 = i % (KDIM/4);
            if (row < OVERLAP)                src = (const float4*)(bg + (size_t)row * KDIM) + c4;
            else if (row < OVERLAP + N_LINES) src = (const float4*)(mn + (size_t)(row - OVERLAP) * KDIM) + c4;
            else                              src = (const float4*)(ed + (size_t)(row - OVERLAP - N_LINES) * KDIM) + c4;
            dst = g_comb + (size_t)i * 4;
        } else if (i < COMB4 + W14) {
            int j = i - COMB4;
            src = (const float4*)w1 + j;
            dst = g_w1 + (size_t)j * 4;
        } else if (i < PREP_TOTAL) {
            int j = i - COMB4 - W14;
            src = (const float4*)w2 + j;
            dst = g_w2 + (size_t)j * 4;
        }
        dsts[t] = dst;
        if (dst) v[t] = *src;
    }
    #pragma unroll
    for (int t = 0; t < 4; t++) {
        if (dsts[t]) {
            __half2* d2 = (__half2*)dsts[t];
            d2[0] = __floats2half2_rn(v[t].x, v[t].y);
            d2[1] = __floats2half2_rn(v[t].z, v[t].w);
        }
    }
}

// ---------------------------------------------------------------------------
// GEMM1: BM=128, BN=128, BK=64, 8 warps (2x4), warp tile 64x32,
// 3-stage cp.async, 2 CTAs/SM. fp16 out. M-sliced via bm0.
// ---------------------------------------------------------------------------
#define STAGE1_BYTES 32768
#define NSTAGE       3
#define GEMM1_SMEM   (NSTAGE * STAGE1_BYTES)

__device__ __forceinline__ void load_stage1(uint32_t smb, int stage,
                                            const __half* A, const __half* B,
                                            int bm, int bn, int k0, int tid)
{
    const uint32_t base = smb + stage * STAGE1_BYTES;
    #pragma unroll
    for (int i = 0; i < 4; i++) {
        int idx = tid + i * 256;
        int row = idx >> 3, c = idx & 7;
        const char* ga = (const char*)(A + (size_t)(bm + row) * KDIM + k0 + c * 8);
        CP_ASYNC16(base + swz64(row, c), ga);
        const char* gb = (const char*)(B + (size_t)(bn + row) * KDIM + k0 + c * 8);
        CP_ASYNC16(base + 16384 + swz64(row, c), gb);
    }
}

__global__ __launch_bounds__(256, 2)
void gemm1_fp16(const __half* __restrict__ A, const __half* __restrict__ B,
                const float* __restrict__ bias, __half* __restrict__ C, int bm0)
{
    extern __shared__ char sm[];
    const uint32_t smb = smem_u32(sm);
    const int tid  = threadIdx.x;
    const int lane = tid & 31;
    const int wid  = tid >> 5;
    const int wm   = wid & 1;
    const int wn   = wid >> 1;
    const int bm = (bm0 + blockIdx.y) * 128;
    const int bn = blockIdx.x * 128;

    float acc[4][4][4];
    #pragma unroll
    for (int i = 0; i < 4; i++)
        #pragma unroll
        for (int j = 0; j < 4; j++)
            #pragma unroll
            for (int r = 0; r < 4; r++) acc[i][j][r] = 0.f;

    load_stage1(smb, 0, A, B, bm, bn, 0, tid);
    CP_COMMIT();
    load_stage1(smb, 1, A, B, bm, bn, BK, tid);
    CP_COMMIT();

    const int lane15 = lane & 15;
    const int aChunkSel = lane >> 4;
    const int bRow = ((lane & 16) >> 1) + (lane & 7);
    const int bChunkSel = (lane >> 3) & 1;

    int stage = 0;
    for (int c = 0; c < CHUNKS; c++) {
        if (c == CHUNKS - 1) { CP_WAIT0(); } else { CP_WAIT1(); }
        __syncthreads();
        if (c + 2 < CHUNKS) {
            int ns = stage + 2; if (ns >= NSTAGE) ns -= NSTAGE;
            load_stage1(smb, ns, A, B, bm, bn, (c + 2) * BK, tid);
            CP_COMMIT();
        }
        const uint32_t base = smb + stage * STAGE1_BYTES;

        #pragma unroll
        for (int ks = 0; ks < 4; ks++) {
            const int c0 = ks * 2;
            uint32_t af[4][4], bf[2][4];
            #pragma unroll
            for (int mt = 0; mt < 4; mt++) {
                int row = wm * 64 + mt * 16 + lane15;
                LDSM4(af[mt], base + swz64(row, c0 + aChunkSel));
            }
            #pragma unroll
            for (int bt = 0; bt < 2; bt++) {
                int row = wn * 32 + bt * 16 + bRow;
                LDSM4(bf[bt], base + 16384 + swz64(row, c0 + bChunkSel));
            }
            #pragma unroll
            for (int mt = 0; mt < 4; mt++)
                #pragma unroll
                for (int nt = 0; nt < 4; nt++) {
                    const uint32_t* bp = bf[nt >> 1] + ((nt & 1) << 1);
                    MMA16816(acc[mt][nt], af[mt], bp[0], bp[1]);
                }
        }
        stage++; if (stage >= NSTAGE) stage = 0;
    }

    #pragma unroll
    for (int mt = 0; mt < 4; mt++) {
        int m0 = bm + wm * 64 + mt * 16 + (lane >> 2);
        #pragma unroll
        for (int nt = 0; nt < 4; nt++) {
            int n = bn + wn * 32 + nt * 8 + (lane & 3) * 2;
            float bx = bias[n], by = bias[n + 1];
            *(__half2*)(C + (size_t)m0 * QKV_N + n) =
                __floats2half2_rn(acc[mt][nt][0] + bx, acc[mt][nt][1] + by);
            *(__half2*)(C + (size_t)(m0 + 8) * QKV_N + n) =
                __floats2half2_rn(acc[mt][nt][2] + bx, acc[mt][nt][3] + by);
        }
    }
}

// ---------------------------------------------------------------------------
// GEMM2: BM=128, BN=128, BK=64, 128 threads (4 warps 2x2), warp tile 64x64,
// 3-stage cp.async, 2 CTAs/SM. fp32 out. M-sliced via bm0.
// ---------------------------------------------------------------------------
#define STAGE2_BYTES 32768
#define GEMM2_SMEM   (NSTAGE * STAGE2_BYTES)

__device__ __forceinline__ void load_stage2(uint32_t smb, int stage,
                                            const __half* A, const __half* B,
                                            int bm, int bn, int k0, int tid)
{
    const uint32_t base = smb + stage * STAGE2_BYTES;
    #pragma unroll
    for (int i = 0; i < 8; i++) {
        int idx = tid + i * 128;
        int row = idx >> 3, c = idx & 7;
        const char* ga = (const char*)(A + (size_t)(bm + row) * KDIM + k0 + c * 8);
        CP_ASYNC16(base + swz64(row, c), ga);
    }
    #pragma unroll
    for (int i = 0; i < 8; i++) {
        int idx = tid + i * 128;
        int row = idx >> 3, c = idx & 7;
        const char* gb = (const char*)(B + (size_t)(bn + row) * KDIM + k0 + c * 8);
        CP_ASYNC16(base + 16384 + swz64(row, c), gb);
    }
}

__global__ __launch_bounds__(128, 2)
void gemm2_fp16(const __half* __restrict__ A, const __half* __restrict__ B,
                const float* __restrict__ bias, float* __restrict__ C, int bm0)
{
    extern __shared__ char sm[];
    const uint32_t smb = smem_u32(sm);
    const int tid  = threadIdx.x;
    const int lane = tid & 31;
    const int wid  = tid >> 5;
    const int wm   = wid & 1;
    const int wn   = wid >> 1;
    const int bm = (bm0 + blockIdx.y) * 128;
    const int bn = blockIdx.x * 128;

    float acc[4][8][4];
    #pragma unroll
    for (int i = 0; i < 4; i++)
        #pragma unroll
        for (int j = 0; j < 8; j++)
            #pragma unroll
            for (int r = 0; r < 4; r++) acc[i][j][r] = 0.f;

    load_stage2(smb, 0, A, B, bm, bn, 0, tid);
    CP_COMMIT();
    load_stage2(smb, 1, A, B, bm, bn, BK, tid);
    CP_COMMIT();

    const int lane15 = lane & 15;
    const int aChunkSel = lane >> 4;
    const int bRow = ((lane & 16) >> 1) + (lane & 7);
    const int bChunkSel = (lane >> 3) & 1;

    int stage = 0;
    for (int c = 0; c < CHUNKS; c++) {
        if (c == CHUNKS - 1) { CP_WAIT0(); } else { CP_WAIT1(); }
        __syncthreads();
        if (c + 2 < CHUNKS) {
            int ns = stage + 2; if (ns >= NSTAGE) ns -= NSTAGE;
            load_stage2(smb, ns, A, B, bm, bn, (c + 2) * BK, tid);
            CP_COMMIT();
        }
        const uint32_t base = smb + stage * STAGE2_BYTES;

        #pragma unroll
        for (int ks = 0; ks < 4; ks++) {
            const int c0 = ks * 2;
            uint32_t af[4][4], bf[4][4];
            #pragma unroll
            for (int mt = 0; mt < 4; mt++) {
                int row = wm * 64 + mt * 16 + lane15;
                LDSM4(af[mt], base + swz64(row, c0 + aChunkSel));
            }
            #pragma unroll
            for (int bt = 0; bt < 4; bt++) {
                int row = wn * 64 + bt * 16 + bRow;
                LDSM4(bf[bt], base + 16384 + swz64(row, c0 + bChunkSel));
            }
            #pragma unroll
            for (int mt = 0; mt < 4; mt++)
                #pragma unroll
                for (int nt = 0; nt < 8; nt++) {
                    const uint32_t* bp = bf[nt >> 1] + ((nt & 1) << 1);
                    MMA16816(acc[mt][nt], af[mt], bp[0], bp[1]);
                }
        }
        stage++; if (stage >= NSTAGE) stage = 0;
    }

    #pragma unroll
    for (int mt = 0; mt < 4; mt++) {
        int m0 = bm + wm * 64 + mt * 16 + (lane >> 2);
        #pragma unroll
        for (int nt = 0; nt < 8; nt++) {
            int n = bn + wn * 64 + nt * 8 + (lane & 3) * 2;
            float bx = bias[n], by = bias[n + 1];
            *(float2*)(C + (size_t)m0 * (2*D_MODEL) + D_MODEL + n) =
                make_float2(acc[mt][nt][0] + bx, acc[mt][nt][1] + by);
            *(float2*)(C + (size_t)(m0 + 8) * (2*D_MODEL) + D_MODEL + n) =
                make_float2(acc[mt][nt][2] + bx, acc[mt][nt][3] + by);
        }
    }
}

// ---------------------------------------------------------------------------
// Attention slice + fused main copy.
// ---------------------------------------------------------------------------
__global__ __launch_bounds__(256)
void attn_kernel(const __half* __restrict__ P, __half* __restrict__ ctx,
                 const float* __restrict__ mn, float* __restrict__ out, int lbase)
{
    const int warp = threadIdx.x >> 5;
    const int lane = threadIdx.x & 31;
    const int n    = lbase + blockIdx.x * 4 + (warp >> 1);
    const int half = warp & 1;
    const int dimoff = half * 384 + (lane >> 3) * HD + (lane & 7) * 12;

    const float scale = rsqrtf((float)HD);

    float qf[12];
    {
        const uint2* qp = (const uint2*)(P + (size_t)(n + OVERLAP) * QKV_N + dimoff);
        #pragma unroll
        for (int t = 0; t < 3; t++) {
            uint2 u = qp[t];
            const __half2* h2 = (const __half2*)&u;
            #pragma unroll
            for (int j = 0; j < 2; j++) {
                float2 f = __half22float2(h2[j]);
                qf[t*4 + 2*j]     = f.x * scale;
                qf[t*4 + 2*j + 1] = f.y * scale;
            }
        }
    }

    float s[W_KEYS];
    #pragma unroll
    for (int w = 0; w < W_KEYS; w++) {
        int off = (w < 8) ? (-OVERLAP + GAP * w) : (GAP * (w - 7));
        const uint2* kp = (const uint2*)(P + (size_t)(n + OVERLAP + off) * QKV_N + D_MODEL + dimoff);
        float p = 0.f;
        #pragma unroll
        for (int t = 0; t < 3; t++) {
            uint2 u = kp[t];
            const __half2* h2 = (const __half2*)&u;
            #pragma unroll
            for (int j = 0; j < 2; j++) {
                float2 f = __half22float2(h2[j]);
                p = fmaf(qf[t*4 + 2*j],     f.x, p);
                p = fmaf(qf[t*4 + 2*j + 1], f.y, p);
            }
        }
        p += __shfl_xor_sync(0xffffffffu, p, 1);
        p += __shfl_xor_sync(0xffffffffu, p, 2);
        p += __shfl_xor_sync(0xffffffffu, p, 4);
        s[w] = p;
    }

    float m = s[0];
    #pragma unroll
    for (int w = 1; w < W_KEYS; w++) m = fmaxf(m, s[w]);
    float sum = 0.f;
    #pragma unroll
    for (int w = 0; w < W_KEYS; w++) { s[w] = __expf(s[w] - m); sum += s[w]; }
    float inv = 1.f / sum;

    float c[12];
    #pragma unroll
    for (int j = 0; j < 12; j++) c[j] = 0.f;
    #pragma unroll
    for (int w = 0; w < W_KEYS; w++) {
        int off = (w < 8) ? (-OVERLAP + GAP * w) : (GAP * (w - 7));
        const uint2* vp = (const uint2*)(P + (size_t)(n + OVERLAP + off) * QKV_N + 2*D_MODEL + dimoff);
        float p = s[w] * inv;
        #pragma unroll
        for (int t = 0; t < 3; t++) {
            uint2 u = vp[t];
            const __half2* h2 = (const __half2*)&u;
            #pragma unroll
            for (int j = 0; j < 2; j++) {
                float2 f = __half22float2(h2[j]);
                c[t*4 + 2*j]     = fmaf(p, f.x, c[t*4 + 2*j]);
                c[t*4 + 2*j + 1] = fmaf(p, f.y, c[t*4 + 2*j + 1]);
            }
        }
    }

    uint2* cp = (uint2*)(ctx + (size_t)n * D_MODEL + dimoff);
    #pragma unroll
    for (int t = 0; t < 3; t++) {
        uint2 u;
        __half2* h2 = (__half2*)&u;
        h2[0] = __floats2half2_rn(c[t*4 + 0], c[t*4 + 1]);
        h2[1] = __floats2half2_rn(c[t*4 + 2], c[t*4 + 3]);
        cp[t] = u;
    }

    {
        int b0 = (lbase / 4 + blockIdx.x) * 768 + threadIdx.x;
        #pragma unroll
        for (int i = 0; i < 3; i++) {
            int idx = b0 + i * 256;
            int row = idx / 192, c4 = idx % 192;
            ((float4*)(out + (size_t)row * 2 * D_MODEL))[c4] =
                ((const float4*)(mn + (size_t)row * D_MODEL))[c4];
        }
    }
}

// ---------------------------------------------------------------------------
// 4 pipeline lanes with descending priority (static init)
// ---------------------------------------------------------------------------
struct PipeRes {
    cudaStream_t s[NLANES - 1];
    cudaEvent_t ePrep, eG1[NLANES], eG2[NLANES - 1];
    PipeRes() {
        int lo, hi;
        cudaDeviceGetStreamPriorityRange(&lo, &hi);
        for (int i = 0; i < NLANES - 1; i++) {
            int pr = hi + 1 + i;  if (pr > lo) pr = lo;
            cudaStreamCreateWithPriority(&s[i], cudaStreamNonBlocking, pr);
        }
        cudaEventCreateWithFlags(&ePrep, cudaEventDisableTiming);
        for (int i = 0; i < NLANES; i++) cudaEventCreateWithFlags(&eG1[i], cudaEventDisableTiming);
        for (int i = 0; i < NLANES - 1; i++) cudaEventCreateWithFlags(&eG2[i], cudaEventDisableTiming);
    }
};
static PipeRes g_pipe;

// ---------------------------------------------------------------------------
extern "C" void kernel_launch(void* const* d_in, const int* in_sizes, int n_in,
                              void* d_out, int out_size)
{
    const float* mn   = (const float*)d_in[0];
    const float* bg   = (const float*)d_in[1];
    const float* ed   = (const float*)d_in[2];
    const float* wqkv = (const float*)d_in[3];
    const float* bqkv = (const float*)d_in[4];
    const float* wo   = (const float*)d_in[5];
    const float* bo   = (const float*)d_in[6];
    float* out = (float*)d_out;

    void *pP, *pc, *pw1, *pw2, *pcx;
    cudaGetSymbolAddress(&pP,  g_P);
    cudaGetSymbolAddress(&pc,  g_comb);
    cudaGetSymbolAddress(&pw1, g_w1);
    cudaGetSymbolAddress(&pw2, g_w2);
    cudaGetSymbolAddress(&pcx, g_ctx);
    const __half* P  = (const __half*)pP;
    const __half* CB = (const __half*)pc;
    const __half* W1 = (const __half*)pw1;
    const __half* W2 = (const __half*)pw2;
    __half* CX = (__half*)pcx;

    cudaFuncSetAttribute(gemm1_fp16, cudaFuncAttributeMaxDynamicSharedMemorySize, GEMM1_SMEM);
    cudaFuncSetAttribute(gemm2_fp16, cudaFuncAttributeMaxDynamicSharedMemorySize, GEMM2_SMEM);

    // lane slicing:
    // GEMM1 M-tiles (P rows /128): starts {0,17,33,49}, counts {17,16,16,16}
    // attn lines: 2048 per lane; GEMM2 M-tiles: 16 per lane
    const int g1s[NLANES] = {0, 17, 33, 49};
    const int g1c[NLANES] = {17, 16, 16, 16};

    // --- lane 0 on capture (legacy) stream ---
    prep_kernel<<<(PREP_TOTAL + 1023) / 1024, 256>>>(mn, bg, ed, wqkv, wo);
    cudaEventRecord(g_pipe.ePrep, 0);

    {   // G1 slice 0
        dim3 grid(QKV_N / 128, g1c[0]);
        gemm1_fp16<<<grid, 256, GEMM1_SMEM>>>(CB, W1, bqkv, (__half*)pP, g1s[0]);
        cudaEventRecord(g_pipe.eG1[0], 0);
    }

    // --- lanes 1..3: G1 slices (wait prep) ---
    for (int i = 1; i < NLANES; i++) {
        cudaStream_t st = g_pipe.s[i - 1];
        cudaStreamWaitEvent(st, g_pipe.ePrep, 0);
        dim3 grid(QKV_N / 128, g1c[i]);
        gemm1_fp16<<<grid, 256, GEMM1_SMEM, st>>>(CB, W1, bqkv, (__half*)pP, g1s[i]);
        cudaEventRecord(g_pipe.eG1[i], st);
    }

    // --- lane 0: attn slice 0 + G2 slice 0 ---
    attn_kernel<<<512, 256>>>(P, CX, mn, out, 0);
    {
        dim3 grid(D_MODEL / 128, 16);
        gemm2_fp16<<<grid, 128, GEMM2_SMEM>>>(CX, W2, bo, out, 0);
    }

    // --- lanes 1..3: attn_i (waits eG1[i-1]; own G1 same-stream) + G2_i ---
    for (int i = 1; i < NLANES; i++) {
        cudaStream_t st = g_pipe.s[i - 1];
        cudaStreamWaitEvent(st, g_pipe.eG1[i - 1], 0);
        attn_kernel<<<512, 256, 0, st>>>(P, CX, mn, out, 2048 * i);
        dim3 grid(D_MODEL / 128, 16);
        gemm2_fp16<<<grid, 128, GEMM2_SMEM, st>>>(CX, W2, bo, out, 16 * i);
        cudaEventRecord(g_pipe.eG2[i - 1], st);
    }

    // join lanes back to capture stream
    for (int i = 0; i < NLANES - 1; i++)
        cudaStreamWaitEvent(0, g_pipe.eG2[i], 0);
}